// round 2
// baseline (speedup 1.0000x reference)
#include <cuda_runtime.h>
#include <cstdint>

#define DIM   33
#define DIM2  (DIM * DIM)          // 1089
#define NLUT  (DIM * DIM * DIM)    // 35937
#define BATCH 8
#define HW    (1024 * 1024)        // plane size
#define QUADS_PER_PLANE (HW / 4)   // 262144

// AoS-packed LUT: one float4 per cell = (ch0, ch1, ch2, pad).
__device__ float4 g_lut[NLUT];

__global__ void pack_lut_kernel(const float* __restrict__ lut) {
    int i = blockIdx.x * blockDim.x + threadIdx.x;
    if (i < NLUT) {
        g_lut[i] = make_float4(lut[i], lut[i + NLUT], lut[i + 2 * NLUT], 0.0f);
    }
}

__device__ __forceinline__ float4 lerp4(float4 a, float4 b, float w) {
    // a + w*(b-a), componentwise (xyz used)
    float4 r;
    r.x = fmaf(w, b.x - a.x, a.x);
    r.y = fmaf(w, b.y - a.y, a.y);
    r.z = fmaf(w, b.z - a.z, a.z);
    r.w = 0.0f;
    return r;
}

__global__ __launch_bounds__(256)
void apply_lut_kernel(const float* __restrict__ x, float* __restrict__ out) {
    // One thread handles 4 consecutive pixels of one batch image.
    int q = blockIdx.x * blockDim.x + threadIdx.x;          // quad index, [0, BATCH*QUADS_PER_PLANE)
    int b = q >> 18;                                        // q / 262144
    int p = q & (QUADS_PER_PLANE - 1);                      // quad within plane

    const float* xb = x + (size_t)b * 3 * HW + (size_t)p * 4;
    float4 rv = *reinterpret_cast<const float4*>(xb);
    float4 gv = *reinterpret_cast<const float4*>(xb + HW);
    float4 bv = *reinterpret_cast<const float4*>(xb + 2 * HW);

    // binsize = 1.000001 / (DIM-1); t = x / binsize  ->  x * INV
    const float INV = (float)(DIM - 1) / 1.000001f;

    float rin[4] = {rv.x, rv.y, rv.z, rv.w};
    float gin[4] = {gv.x, gv.y, gv.z, gv.w};
    float bin[4] = {bv.x, bv.y, bv.z, bv.w};
    float orr[4], org[4], orb[4];

#pragma unroll
    for (int k = 0; k < 4; k++) {
        float tr = rin[k] * INV;
        float tg = gin[k] * INV;
        float tb = bin[k] * INV;

        // idx = clip(floor(t), 0, DIM-2); t >= 0 here, so trunc == floor.
        int ir = min(max((int)tr, 0), DIM - 2);
        int ig = min(max((int)tg, 0), DIM - 2);
        int ib = min(max((int)tb, 0), DIM - 2);

        float fr = tr - (float)ir;
        float fg = tg - (float)ig;
        float fb = tb - (float)ib;

        int base = ib * DIM2 + ig * DIM + ir;

        float4 c000 = g_lut[base];
        float4 c001 = g_lut[base + 1];
        float4 c010 = g_lut[base + DIM];
        float4 c011 = g_lut[base + DIM + 1];
        float4 c100 = g_lut[base + DIM2];
        float4 c101 = g_lut[base + DIM2 + 1];
        float4 c110 = g_lut[base + DIM2 + DIM];
        float4 c111 = g_lut[base + DIM2 + DIM + 1];

        float4 c00 = lerp4(c000, c001, fr);
        float4 c01 = lerp4(c010, c011, fr);
        float4 c10 = lerp4(c100, c101, fr);
        float4 c11 = lerp4(c110, c111, fr);

        float4 c0 = lerp4(c00, c01, fg);
        float4 c1 = lerp4(c10, c11, fg);

        float4 c = lerp4(c0, c1, fb);

        orr[k] = c.x;
        org[k] = c.y;
        orb[k] = c.z;
    }

    float* ob = out + (size_t)b * 3 * HW + (size_t)p * 4;
    *reinterpret_cast<float4*>(ob)          = make_float4(orr[0], orr[1], orr[2], orr[3]);
    *reinterpret_cast<float4*>(ob + HW)     = make_float4(org[0], org[1], org[2], org[3]);
    *reinterpret_cast<float4*>(ob + 2 * HW) = make_float4(orb[0], orb[1], orb[2], orb[3]);
}

extern "C" void kernel_launch(void* const* d_in, const int* in_sizes, int n_in,
                              void* d_out, int out_size) {
    const float* lut = (const float*)d_in[0];
    const float* x   = (const float*)d_in[1];
    float* out       = (float*)d_out;

    pack_lut_kernel<<<(NLUT + 255) / 256, 256>>>(lut);

    int total_quads = BATCH * QUADS_PER_PLANE;   // 2,097,152
    apply_lut_kernel<<<total_quads / 256, 256>>>(x, out);
}